// round 16
// baseline (speedup 1.0000x reference)
#include <cuda_runtime.h>
#include <cuda_fp16.h>
#include <cstdint>
#include <math.h>

#define MESHN 128
#define M2    16384
#define M3    2097152
#define SW    145
#define PST   137
#define MCUT  33
#define RR    (MCUT*MCUT)
#define TWT_F2 144

// Scratch (static device globals — zero-initialized, no runtime allocation)
__device__ float        g_real[M3];     // paint grid R0
__device__ float        g_realB[M3];    // paint shadow grid R1 (z-shifted by 2)
__device__ unsigned int g_A[M3];
__device__ unsigned int g_B[M3];
__device__ unsigned int g_C[M3];
__device__ uint4        g_G0[M3/2];     // force pairs: cells (2zp, 2zp+1)
__device__ uint4        g_G1[M3/2];     // force pairs: cells (2zp+1, 2zp+2 mod 128)

// ---------------------------------------------------------------------------
__device__ __forceinline__ float2 cadd(float2 a, float2 b){ return make_float2(a.x+b.x, a.y+b.y); }
__device__ __forceinline__ float2 csub(float2 a, float2 b){ return make_float2(a.x-b.x, a.y-b.y); }
__device__ __forceinline__ float2 cmul(float2 a, float2 b){ return make_float2(a.x*b.x-a.y*b.y, a.x*b.y+a.y*b.x); }
template<int SGN>
__device__ __forceinline__ float2 cmulJ(float2 a){ return make_float2((float)(-SGN)*a.y, (float)SGN*a.x); }

__device__ __forceinline__ int nidx(int i){ return i + ((i>>6)<<3); }
__device__ __forceinline__ int pidx(int e){ return nidx(e>>7)*PST + nidx(e&127); }

__device__ __forceinline__ unsigned int h2u(__half2 h){ return *reinterpret_cast<unsigned int*>(&h); }
__device__ __forceinline__ __half2 u2h(unsigned int u){ return *reinterpret_cast<__half2*>(&u); }
__device__ __forceinline__ unsigned int pack_h2(float2 v){ return h2u(__floats2half2_rn(v.x, v.y)); }
__device__ __forceinline__ float2 unpack_h2(unsigned int u){ return __half22float2(u2h(u)); }

__device__ __forceinline__ void build_twt(float2* twt, int t, float sgn){
    if (t < TWT_F2){
        int v = t/9, k2 = t - 9*v;
        float sa, ca;
        __sincosf(sgn * 0.049087385212340526f * (float)(v*k2), &sa, &ca);
        twt[t] = make_float2(ca, sa);
    }
}

template<int SGN>
__device__ __forceinline__ void dft8(float2* a){
    const float R2 = 0.70710678118654752f;
    const float2 W1 = make_float2( R2, (float)SGN*R2);
    const float2 W3 = make_float2(-R2, (float)SGN*R2);
    float2 t0=cadd(a[0],a[4]), t4=csub(a[0],a[4]);
    float2 t1=cadd(a[1],a[5]), t5=cmul(csub(a[1],a[5]),W1);
    float2 t2=cadd(a[2],a[6]), t6=cmulJ<SGN>(csub(a[2],a[6]));
    float2 t3=cadd(a[3],a[7]), t7=cmul(csub(a[3],a[7]),W3);
    float2 u0=cadd(t0,t2), u2=csub(t0,t2);
    float2 u1=cadd(t1,t3), u3=cmulJ<SGN>(csub(t1,t3));
    a[0]=cadd(u0,u1); a[4]=csub(u0,u1);
    a[2]=cadd(u2,u3); a[6]=csub(u2,u3);
    float2 v0=cadd(t4,t6), v2=csub(t4,t6);
    float2 v1=cadd(t5,t7), v3=cmulJ<SGN>(csub(t5,t7));
    a[1]=cadd(v0,v1); a[5]=csub(v0,v1);
    a[3]=cadd(v2,v3); a[7]=csub(v2,v3);
}

template<int SGN>
__device__ __forceinline__ void fft128(float2* r, float2* s, int L, int v,
                                       const float2* twt){
    __syncwarp();
    dft8<SGN>(r);
    const float2* tv = twt + v*9;
    #pragma unroll
    for(int k2=1;k2<8;k2++) r[k2]=cmul(r[k2], tv[k2]);
    float2* sl = s + L*SW;
    #pragma unroll
    for(int k2=0;k2<8;k2++) sl[k2*18 + v] = r[k2];
    __syncwarp();
    int k2 = v>>1, t1 = v&1;
    #pragma unroll
    for(int q=0;q<8;q++) r[q] = sl[k2*18 + t1 + 2*q];
    __syncwarp();
    dft8<SGN>(r);
    if (t1){
        const float cj[8] = {1.f, 0.92387953251128674f, 0.70710678118654752f,
                             0.38268343236508977f, 0.f, -0.38268343236508977f,
                             -0.70710678118654752f, -0.92387953251128674f};
        const float sj[8] = {0.f, 0.38268343236508977f, 0.70710678118654752f,
                             0.92387953251128674f, 1.f, 0.92387953251128674f,
                             0.70710678118654752f, 0.38268343236508977f};
        #pragma unroll
        for(int j=1;j<8;j++)
            r[j]=cmul(r[j], make_float2(cj[j], (float)SGN*sj[j]));
    }
    #pragma unroll
    for(int j=0;j<8;j++){
        float px = __shfl_xor_sync(0xFFFFFFFFu, r[j].x, 1);
        float py = __shfl_xor_sync(0xFFFFFFFFu, r[j].y, 1);
        if (t1==0) r[j] = make_float2(r[j].x+px, r[j].y+py);
        else       r[j] = make_float2(px-r[j].x, py-r[j].y);
    }
}

__device__ __forceinline__ void plane_fft2d_xy(float2* plane, float2* scratch,
                                               const float2* twt){
    int tid=threadIdx.x, L=tid>>4, v=tid&15, k2=v>>1, t1=v&1;
    float2 r[8];
    #pragma unroll
    for(int it=0; it<2; it++){
        int p0 = it*64 + (L & ~1);
        int minabs = (p0 < 64) ? p0 : 127 - p0;
        if (minabs <= MCUT){
            float2* row = plane + nidx(it*64+L)*PST;
            #pragma unroll
            for(int n2=0;n2<8;n2++) r[n2]=row[nidx(v+16*n2)];
            fft128<1>(r, scratch, L, v, twt);
            #pragma unroll
            for(int j=0;j<8;j++) row[nidx(k2+8*j+64*t1)]=r[j];
        }
    }
    __syncthreads();
    #pragma unroll
    for(int it=0; it<2; it++){
        int zc = nidx(it*64+L);
        #pragma unroll
        for(int n2=0;n2<8;n2++) r[n2]=plane[nidx(v+16*n2)*PST + zc];
        fft128<1>(r, scratch, L, v, twt);
        #pragma unroll
        for(int j=0;j<8;j++) plane[nidx(k2+8*j+64*t1)*PST + zc]=r[j];
    }
    __syncthreads();
}

#define PLANE_F2   (136*PST)
#define SMEM_PLANE ((PLANE_F2 + 64*SW + TWT_F2)*8)

// Forward: (R0 + z-shifted R1) plane -> rFFT-packed 2D FFT -> half2 spectrum.
__global__ void __launch_bounds__(1024, 1)
fft_plane_fwd(const float* __restrict__ r0, const float* __restrict__ r1,
              unsigned int* __restrict__ out){
    extern __shared__ float2 sm[];
    float2* plane = sm; float2* scratch = sm + PLANE_F2;
    float2* twt = sm + PLANE_F2 + 64*SW;
    int tid = threadIdx.x, L = tid>>4, v = tid&15;
    int k2 = v>>1, t1 = v&1;
    build_twt(twt, tid, -1.f);
    size_t base = (size_t)blockIdx.x * M2;
    float2 r[8];
    #pragma unroll
    for(int n2=0;n2<8;n2++){
        int zi = v + 16*n2;
        int zs = (zi - 2) & 127;
        float a0 = r0[base + 2*L*128 + zi]     + r1[base + 2*L*128 + zs];
        float a1 = r0[base + (2*L+1)*128 + zi] + r1[base + (2*L+1)*128 + zs];
        r[n2] = make_float2(a0, a1);
    }
    __syncthreads();
    fft128<-1>(r, scratch, L, v, twt);
    #pragma unroll
    for(int j=0;j<8;j++) scratch[L*SW + nidx(k2+8*j+64*t1)] = r[j];
    __syncthreads();
    #pragma unroll
    for(int k=0;k<16;k++){
        int e = tid + k*1024;
        int y = e>>7, z = e&127, p = y>>1;
        float2 H1 = scratch[p*SW + nidx(z)];
        float2 H2 = scratch[p*SW + nidx((128-z)&127)];
        float2 val;
        if ((y&1)==0) val = make_float2(0.5f*(H1.x+H2.x), 0.5f*(H1.y-H2.y));
        else          val = make_float2(0.5f*(H1.y+H2.y), 0.5f*(H2.x-H1.x));
        plane[pidx(e)] = val;
    }
    __syncthreads();
    if (L <= MCUT){
        int zc = nidx(L);
        #pragma unroll
        for(int n2=0;n2<8;n2++) r[n2] = plane[nidx(v+16*n2)*PST + zc];
        fft128<-1>(r, scratch, L, v, twt);
        #pragma unroll
        for(int j=0;j<8;j++) plane[nidx(k2+8*j+64*t1)*PST + zc] = r[j];
    }
    __syncthreads();
    const float s = 1.f/16384.f;
    #pragma unroll
    for(int k=0;k<16;k++){
        int e = tid + k*1024;
        int y = e>>7, z = e&127;
        int mz = (z < 64) ? z : 128 - z;
        if (mz <= MCUT){
            float2 xy;
            if (z <= MCUT) xy = plane[pidx(e)];
            else {
                int y2 = (128-y)&127, z2 = 128-z;
                xy = plane[nidx(y2)*PST + nidx(z2)];
                xy.y = -xy.y;
            }
            out[base+e] = pack_h2(make_float2(xy.x*s, xy.y*s));
        }
    }
}

// Combined inverse -> dual pair grids G0/G1 (coalesced uint4 stores).
__global__ void __launch_bounds__(1024, 1)
fft_plane_inv(const unsigned int* __restrict__ inXY,
              const unsigned int* __restrict__ inZ,
              uint4* __restrict__ G0, uint4* __restrict__ G1){
    extern __shared__ float2 sm[];
    float2* plane = sm; float2* scratch = sm + PLANE_F2;
    float2* twt = sm + PLANE_F2 + 64*SW;
    int tid = threadIdx.x, L = tid>>4, v = tid&15;
    int k2 = v>>1, t1 = v&1;
    build_twt(twt, tid, 1.f);
    size_t base = (size_t)blockIdx.x * M2;
    float2 r[8];

    // --- Fz plane (Hermitian: rows 0..MCUT computed, 95..127 mirrored) ---
    #pragma unroll
    for(int k=0;k<16;k++){
        int e = tid + k*1024;
        int y = e>>7;
        if (y <= MCUT)      plane[pidx(e)] = unpack_h2(inZ[base+e]);
        else if (y < 95)    plane[pidx(e)] = make_float2(0.f,0.f);
    }
    __syncthreads();
    if (L <= MCUT){
        float2* row = plane + nidx(L)*PST;
        #pragma unroll
        for(int n2=0;n2<8;n2++) r[n2] = row[nidx(v+16*n2)];
        fft128<1>(r, scratch, L, v, twt);
        #pragma unroll
        for(int j=0;j<8;j++) row[nidx(k2+8*j+64*t1)] = r[j];
    }
    __syncthreads();
    #pragma unroll
    for(int k=0;k<16;k++){
        int e = tid + k*1024;
        int y = e>>7;
        if (y >= 95){
            int z = e&127;
            float2 q = plane[nidx(128-y)*PST + nidx(z)];
            plane[pidx(e)] = make_float2(q.x, -q.y);
        }
    }
    __syncthreads();
    {   // packed phase-2: col pair (2L, 2L+1); outputs real
        int zc0 = nidx(2*L), zc1 = nidx(2*L+1);
        #pragma unroll
        for(int n2=0;n2<8;n2++){
            int rb = nidx(v+16*n2)*PST;
            float2 A = plane[rb + zc0];
            float2 Bv = plane[rb + zc1];
            r[n2] = make_float2(A.x - Bv.y, A.y + Bv.x);
        }
        fft128<1>(r, scratch, L, v, twt);
        float* pf = (float*)plane;
        #pragma unroll
        for(int j=0;j<8;j++){
            int i = k2+8*j+64*t1;
            int b2 = nidx(i)*PST;
            pf[2*(b2+zc0)] = r[j].x;
            pf[2*(b2+zc1)] = r[j].y;
        }
    }
    __syncthreads();
    float zreg[16];
    #pragma unroll
    for(int k=0;k<16;k++){
        int e = tid + k*1024;
        int y = e>>7, z0 = e&112;
        int my = (y  < 64) ? y  : 128 - y;
        int mzg = (z0 < 64) ? z0 : 113 - z0;
        bool live = (my*my + mzg*mzg <= RR);
        zreg[k] = plane[pidx(e)].x;
        plane[pidx(e)] = live ? unpack_h2(inXY[base+e]) : make_float2(0.f,0.f);
    }
    __syncthreads();
    plane_fft2d_xy(plane, scratch, twt);
    // stage Fz in scratch, then dual pair stores
    float* fzs = (float*)scratch;
    #pragma unroll
    for(int k=0;k<16;k++){
        int e = tid + k*1024;
        fzs[e] = zreg[k];
    }
    __syncthreads();
    size_t pbase = (size_t)blockIdx.x * 8192;
    #pragma unroll
    for(int k=0;k<16;k++){
        int pp = tid + k*1024;             // 0..16383
        int sel = pp >> 13;                // 0 -> G0, 1 -> G1
        int q = pp & 8191;
        int y = q >> 6, zp = q & 63;
        int z0 = sel ? (2*zp+1) : (2*zp);
        int z1 = sel ? ((2*zp+2)&127) : (2*zp+1);
        int rb = nidx(y)*PST;
        float2 xy0 = plane[rb + nidx(z0)];
        float2 xy1 = plane[rb + nidx(z1)];
        float f0 = fzs[y*128 + z0];
        float f1 = fzs[y*128 + z1];
        uint4 val = make_uint4(pack_h2(xy0), h2u(__floats2half2_rn(f0, 0.f)),
                               pack_h2(xy1), h2u(__floats2half2_rn(f1, 0.f)));
        (sel ? G1 : G0)[pbase + q] = val;
    }
}

// ---------------------------------------------------------------------------
__global__ void __launch_bounds__(256)
fft_x_fused(const unsigned int* __restrict__ in,
            unsigned int* __restrict__ outXY,
            unsigned int* __restrict__ outZ){
    __shared__ float2 s[16*SW];
    __shared__ float2 twtF[TWT_F2], twtI[TWT_F2];
    int base = blockIdx.x*16;
    {
        int y  = base >> 7;
        int z0 = base & 127;
        int my = (y  < 64) ? y  : 128 - y;
        int mz = (z0 < 64) ? z0 : 113 - z0;
        if (my*my + mz*mz > RR) return;
    }
    int tid=threadIdx.x, L=tid>>4, v=tid&15;
    build_twt(twtF, tid, -1.f);
    if (tid >= TWT_F2) build_twt(twtI, tid - TWT_F2, 1.f);
    else if (tid < 2*TWT_F2 - 256) build_twt(twtI, tid + (256 - TWT_F2), 1.f);
    float2 r[8];
    #pragma unroll
    for(int k=0;k<8;k++){ int e=tid+k*256; int i=e>>4, l=e&15;
        s[l*SW+nidx(i)] = unpack_h2(in[base + l + i*M2]); }
    __syncthreads();
    #pragma unroll
    for(int n2=0;n2<8;n2++) r[n2] = s[L*SW + nidx(v + 16*n2)];
    fft128<-1>(r, s, L, v, twtF);

    int k2=v>>1, t1=v&1;
    int ylz = base + L;
    int y = ylz>>7, z = ylz&127;
    const float ku = 0.049087385212340526f;
    float ky = (float)((y<64)?y:y-128)*ku;
    float kz = (float)((z<64)?z:z-128)*ku;
    float kyz2 = ky*ky + kz*kz;
    float2 fz[8];
    #pragma unroll
    for(int j=0;j<8;j++){
        int i = k2+8*j+64*t1;
        float kx = (float)((i<64)?i:i-128)*ku;
        float kk = kx*kx + kyz2;
        float coef = 0.f;
        if (kk > 0.f){
            float ikk = 1.f/kk;
            coef = -ikk * __expf(-0.09f*ikk - kk*kk) * (1.f/128.f);
        }
        float pr = r[j].x*coef, pi = r[j].y*coef;
        r[j]  = make_float2(pr*ky + pi*kx, pi*ky - pr*kx);
        fz[j] = make_float2(pi*kz, -pr*kz);
    }

    #pragma unroll
    for(int j=0;j<8;j++){ int i=k2+8*j+64*t1; s[L*SW+nidx(i)] = r[j]; }
    __syncwarp();
    #pragma unroll
    for(int n2=0;n2<8;n2++) r[n2] = s[L*SW + nidx(v + 16*n2)];
    fft128<1>(r, s, L, v, twtI);
    #pragma unroll
    for(int j=0;j<8;j++){ int i=k2+8*j+64*t1; s[L*SW+nidx(i)] = r[j]; }
    __syncthreads();
    #pragma unroll
    for(int k=0;k<8;k++){ int e=tid+k*256; int i=e>>4, l=e&15;
        outXY[base + l + i*M2] = pack_h2(s[l*SW+nidx(i)]); }
    __syncthreads();

    #pragma unroll
    for(int j=0;j<8;j++){ int i=k2+8*j+64*t1; s[L*SW+nidx(i)] = fz[j]; }
    __syncwarp();
    #pragma unroll
    for(int n2=0;n2<8;n2++) r[n2] = s[L*SW + nidx(v + 16*n2)];
    fft128<1>(r, s, L, v, twtI);
    #pragma unroll
    for(int j=0;j<8;j++){ int i=k2+8*j+64*t1; s[L*SW+nidx(i)] = r[j]; }
    __syncthreads();
    #pragma unroll
    for(int k=0;k<8;k++){ int e=tid+k*256; int i=e>>4, l=e&15;
        outZ[base + l + i*M2] = pack_h2(s[l*SW+nidx(i)]); }
}

// ---------------------------------------------------------------------------
// Paint: every particle does exactly 4 aligned float4 REDs.
__global__ void paint_kernel(const float* __restrict__ pos,
                             float* __restrict__ R0, float* __restrict__ R1,
                             int N){
    int n = blockIdx.x*256 + threadIdx.x;
    if (n >= N) return;
    float px = pos[3*n+0], py = pos[3*n+1], pz = pos[3*n+2];
    float f0x = floorf(px), f0y = floorf(py), f0z = floorf(pz);
    int ix = ((int)f0x)&127, iy = ((int)f0y)&127, iz = ((int)f0z)&127;
    float dx = px-f0x, dy = py-f0y, dz = pz-f0z;
    float wx[2]={1.f-dx,dx}, wy[2]={1.f-dy,dy};
    float wz0 = 1.f-dz, wz1 = dz;
    int xi[2]={ix,(ix+1)&127}, yi[2]={iy,(iy+1)&127};
    int lanez = iz & 3;
    float* Gd;
    int zb;
    float v0=0.f, v1=0.f, v2=0.f, v3=0.f;
    if (lanez == 0){ Gd = R0; zb = iz & ~3;       v0=wz0; v1=wz1; }
    else if (lanez == 1){ Gd = R0; zb = iz & ~3;  v1=wz0; v2=wz1; }
    else if (lanez == 2){ Gd = R0; zb = iz & ~3;  v2=wz0; v3=wz1; }
    else { Gd = R1; zb = (iz-2) & ~3;             v1=wz0; v2=wz1; }
#pragma unroll
    for(int a=0;a<2;a++)
#pragma unroll
    for(int b=0;b<2;b++){
        float wab = wx[a]*wy[b];
        atomicAdd((float4*)(Gd + xi[a]*M2 + yi[b]*MESHN + zb),
                  make_float4(wab*v0, wab*v1, wab*v2, wab*v3));
    }
}

__global__ void copy_pos_kernel(const float4* __restrict__ pos4,
                                float4* __restrict__ out4, int n4){
    int i = blockIdx.x*256 + threadIdx.x;
    if (i < n4) out4[i] = pos4[i];
}

// Gather from dual pair grid: 4 aligned 16B loads per particle; 2 particles
// per thread for load-level parallelism.
__device__ __forceinline__ void gather_one(int n,
                              const float* __restrict__ pos,
                              const float* __restrict__ vel,
                              float sc,
                              const uint4* __restrict__ G0,
                              const uint4* __restrict__ G1,
                              float* __restrict__ ov){
    float px = pos[3*n+0], py = pos[3*n+1], pz = pos[3*n+2];
    float f0x = floorf(px), f0y = floorf(py), f0z = floorf(pz);
    int ix = ((int)f0x)&127, iy = ((int)f0y)&127, iz = ((int)f0z)&127;
    float dx = px-f0x, dy = py-f0y, dz = pz-f0z;
    float wx[2]={1.f-dx,dx}, wy[2]={1.f-dy,dy};
    float wz0 = 1.f-dz, wz1 = dz;
    int xi[2]={ix,(ix+1)&127}, yi[2]={iy,(iy+1)&127};
    const uint4* Gb = (iz & 1) ? G1 : G0;
    int zp = iz >> 1;
    uint4 u[4];
#pragma unroll
    for(int a=0;a<2;a++)
#pragma unroll
    for(int b=0;b<2;b++)
        u[a*2+b] = Gb[xi[a]*8192 + yi[b]*64 + zp];
    float fx=0.f, fy=0.f, fzv=0.f;
#pragma unroll
    for(int a=0;a<2;a++)
#pragma unroll
    for(int b=0;b<2;b++){
        uint4 u4 = u[a*2+b];
        float2 xy0 = unpack_h2(u4.x);
        float  z0v = __low2float(u2h(u4.y));
        float2 xy1 = unpack_h2(u4.z);
        float  z1v = __low2float(u2h(u4.w));
        float w = wx[a]*wy[b];
        float w0 = w*wz0, w1 = w*wz1;
        fx  += w0*xy0.x + w1*xy1.x;
        fy  += w0*xy0.y + w1*xy1.y;
        fzv += w0*z0v  + w1*z1v;
    }
    ov[3*n+0]=vel[3*n+0]+fx*sc;
    ov[3*n+1]=vel[3*n+1]+fy*sc;
    ov[3*n+2]=vel[3*n+2]+fzv*sc;
}

__global__ void gather_kernel(const float* __restrict__ pos,
                              const float* __restrict__ vel,
                              const float* __restrict__ drift,
                              const uint4* __restrict__ G0,
                              const uint4* __restrict__ G1,
                              float* __restrict__ out, int N){
    int t = blockIdx.x*256 + threadIdx.x;
    float sc = 0.2f / drift[0];
    float* ov = out + (size_t)3*N;
    int n0 = 2*t, n1 = 2*t+1;
    if (n0 < N) gather_one(n0, pos, vel, sc, G0, G1, ov);
    if (n1 < N) gather_one(n1, pos, vel, sc, G0, G1, ov);
}

// ---------------------------------------------------------------------------
extern "C" void kernel_launch(void* const* d_in, const int* in_sizes, int n_in,
                              void* d_out, int out_size){
    const float* pos   = (const float*)d_in[0];
    const float* vel   = (const float*)d_in[1];
    const float* drift = (const float*)d_in[2];
    float* out = (float*)d_out;
    int N = in_sizes[0] / 3;

    void *pR0,*pR1,*pA,*pB,*pC,*pG0,*pG1;
    cudaGetSymbolAddress(&pR0, g_real);
    cudaGetSymbolAddress(&pR1, g_realB);
    cudaGetSymbolAddress(&pA, g_A);
    cudaGetSymbolAddress(&pB, g_B);
    cudaGetSymbolAddress(&pC, g_C);
    cudaGetSymbolAddress(&pG0, g_G0);
    cudaGetSymbolAddress(&pG1, g_G1);
    float* R0 = (float*)pR0;
    float* R1 = (float*)pR1;
    unsigned int* A = (unsigned int*)pA;
    unsigned int* B = (unsigned int*)pB;
    unsigned int* C = (unsigned int*)pC;
    uint4* G0 = (uint4*)pG0;
    uint4* G1 = (uint4*)pG1;

    cudaFuncSetAttribute(fft_plane_fwd, cudaFuncAttributeMaxDynamicSharedMemorySize, SMEM_PLANE);
    cudaFuncSetAttribute(fft_plane_inv, cudaFuncAttributeMaxDynamicSharedMemorySize, SMEM_PLANE);

    cudaStream_t s1;
    cudaEvent_t ev0, ev1;
    cudaStreamCreateWithFlags(&s1, cudaStreamNonBlocking);
    cudaEventCreateWithFlags(&ev0, cudaEventDisableTiming);
    cudaEventCreateWithFlags(&ev1, cudaEventDisableTiming);

    cudaEventRecord(ev0, 0);
    cudaStreamWaitEvent(s1, ev0, 0);
    int n4 = (3*N)/4;
    copy_pos_kernel<<<(n4+255)/256, 256, 0, s1>>>((const float4*)pos, (float4*)out, n4);
    cudaEventRecord(ev1, s1);

    cudaMemsetAsync(R0, 0, (size_t)M3*sizeof(float), 0);
    cudaMemsetAsync(R1, 0, (size_t)M3*sizeof(float), 0);
    paint_kernel<<<(N+255)/256, 256>>>(pos, R0, R1, N);

    fft_plane_fwd<<<128, 1024, SMEM_PLANE>>>(R0, R1, B);
    fft_x_fused<<<1024, 256>>>(B, A, C);
    fft_plane_inv<<<128, 1024, SMEM_PLANE>>>(A, C, G0, G1);

    cudaStreamWaitEvent(0, ev1, 0);
    int nt = (N + 1) / 2;
    gather_kernel<<<(nt+255)/256, 256>>>(pos, vel, drift, G0, G1, out, N);
}

// round 17
// speedup vs baseline: 1.0348x; 1.0348x over previous
#include <cuda_runtime.h>
#include <cuda_fp16.h>
#include <cstdint>
#include <math.h>

#define MESHN 128
#define M2    16384
#define M3    2097152
#define SW    145
#define PST   137
#define MCUT  33
#define RR    (MCUT*MCUT)
#define TWT_F2 144

// Scratch (static device globals — zero-initialized, no runtime allocation)
__device__ float        g_real[M3];     // paint grid R0
__device__ float        g_realB[M3];    // paint shadow grid R1 (z-shifted by 2)
__device__ unsigned int g_A[M3];
__device__ unsigned int g_B[M3];
__device__ unsigned int g_C[M3];
// Quad force grid: 4 parity variants (py,pz), each entry = 2 uint4 = 32B
__device__ uint4        g_Q[4u * 128u * 4096u * 2u];   // 64 MB

// ---------------------------------------------------------------------------
__device__ __forceinline__ float2 cadd(float2 a, float2 b){ return make_float2(a.x+b.x, a.y+b.y); }
__device__ __forceinline__ float2 csub(float2 a, float2 b){ return make_float2(a.x-b.x, a.y-b.y); }
__device__ __forceinline__ float2 cmul(float2 a, float2 b){ return make_float2(a.x*b.x-a.y*b.y, a.x*b.y+a.y*b.x); }
template<int SGN>
__device__ __forceinline__ float2 cmulJ(float2 a){ return make_float2((float)(-SGN)*a.y, (float)SGN*a.x); }

__device__ __forceinline__ int nidx(int i){ return i + ((i>>6)<<3); }
__device__ __forceinline__ int pidx(int e){ return nidx(e>>7)*PST + nidx(e&127); }

__device__ __forceinline__ unsigned int h2u(__half2 h){ return *reinterpret_cast<unsigned int*>(&h); }
__device__ __forceinline__ __half2 u2h(unsigned int u){ return *reinterpret_cast<__half2*>(&u); }
__device__ __forceinline__ unsigned int pack_h2(float2 v){ return h2u(__floats2half2_rn(v.x, v.y)); }
__device__ __forceinline__ float2 unpack_h2(unsigned int u){ return __half22float2(u2h(u)); }

__device__ __forceinline__ void build_twt(float2* twt, int t, float sgn){
    if (t < TWT_F2){
        int v = t/9, k2 = t - 9*v;
        float sa, ca;
        __sincosf(sgn * 0.049087385212340526f * (float)(v*k2), &sa, &ca);
        twt[t] = make_float2(ca, sa);
    }
}

template<int SGN>
__device__ __forceinline__ void dft8(float2* a){
    const float R2 = 0.70710678118654752f;
    const float2 W1 = make_float2( R2, (float)SGN*R2);
    const float2 W3 = make_float2(-R2, (float)SGN*R2);
    float2 t0=cadd(a[0],a[4]), t4=csub(a[0],a[4]);
    float2 t1=cadd(a[1],a[5]), t5=cmul(csub(a[1],a[5]),W1);
    float2 t2=cadd(a[2],a[6]), t6=cmulJ<SGN>(csub(a[2],a[6]));
    float2 t3=cadd(a[3],a[7]), t7=cmul(csub(a[3],a[7]),W3);
    float2 u0=cadd(t0,t2), u2=csub(t0,t2);
    float2 u1=cadd(t1,t3), u3=cmulJ<SGN>(csub(t1,t3));
    a[0]=cadd(u0,u1); a[4]=csub(u0,u1);
    a[2]=cadd(u2,u3); a[6]=csub(u2,u3);
    float2 v0=cadd(t4,t6), v2=csub(t4,t6);
    float2 v1=cadd(t5,t7), v3=cmulJ<SGN>(csub(t5,t7));
    a[1]=cadd(v0,v1); a[5]=csub(v0,v1);
    a[3]=cadd(v2,v3); a[7]=csub(v2,v3);
}

template<int SGN>
__device__ __forceinline__ void fft128(float2* r, float2* s, int L, int v,
                                       const float2* twt){
    __syncwarp();
    dft8<SGN>(r);
    const float2* tv = twt + v*9;
    #pragma unroll
    for(int k2=1;k2<8;k2++) r[k2]=cmul(r[k2], tv[k2]);
    float2* sl = s + L*SW;
    #pragma unroll
    for(int k2=0;k2<8;k2++) sl[k2*18 + v] = r[k2];
    __syncwarp();
    int k2 = v>>1, t1 = v&1;
    #pragma unroll
    for(int q=0;q<8;q++) r[q] = sl[k2*18 + t1 + 2*q];
    __syncwarp();
    dft8<SGN>(r);
    if (t1){
        const float cj[8] = {1.f, 0.92387953251128674f, 0.70710678118654752f,
                             0.38268343236508977f, 0.f, -0.38268343236508977f,
                             -0.70710678118654752f, -0.92387953251128674f};
        const float sj[8] = {0.f, 0.38268343236508977f, 0.70710678118654752f,
                             0.92387953251128674f, 1.f, 0.92387953251128674f,
                             0.70710678118654752f, 0.38268343236508977f};
        #pragma unroll
        for(int j=1;j<8;j++)
            r[j]=cmul(r[j], make_float2(cj[j], (float)SGN*sj[j]));
    }
    #pragma unroll
    for(int j=0;j<8;j++){
        float px = __shfl_xor_sync(0xFFFFFFFFu, r[j].x, 1);
        float py = __shfl_xor_sync(0xFFFFFFFFu, r[j].y, 1);
        if (t1==0) r[j] = make_float2(r[j].x+px, r[j].y+py);
        else       r[j] = make_float2(px-r[j].x, py-r[j].y);
    }
}

__device__ __forceinline__ void plane_fft2d_xy(float2* plane, float2* scratch,
                                               const float2* twt){
    int tid=threadIdx.x, L=tid>>4, v=tid&15, k2=v>>1, t1=v&1;
    float2 r[8];
    #pragma unroll
    for(int it=0; it<2; it++){
        int p0 = it*64 + (L & ~1);
        int minabs = (p0 < 64) ? p0 : 127 - p0;
        if (minabs <= MCUT){
            float2* row = plane + nidx(it*64+L)*PST;
            #pragma unroll
            for(int n2=0;n2<8;n2++) r[n2]=row[nidx(v+16*n2)];
            fft128<1>(r, scratch, L, v, twt);
            #pragma unroll
            for(int j=0;j<8;j++) row[nidx(k2+8*j+64*t1)]=r[j];
        }
    }
    __syncthreads();
    #pragma unroll
    for(int it=0; it<2; it++){
        int zc = nidx(it*64+L);
        #pragma unroll
        for(int n2=0;n2<8;n2++) r[n2]=plane[nidx(v+16*n2)*PST + zc];
        fft128<1>(r, scratch, L, v, twt);
        #pragma unroll
        for(int j=0;j<8;j++) plane[nidx(k2+8*j+64*t1)*PST + zc]=r[j];
    }
    __syncthreads();
}

#define PLANE_F2   (136*PST)
#define SMEM_PLANE ((PLANE_F2 + 64*SW + TWT_F2)*8)

// Forward: (R0 + shifted R1) plane -> 2D FFT (rFFT-packed) -> half2 spectrum.
__global__ void __launch_bounds__(1024, 1)
fft_plane_fwd(const float* __restrict__ r0, const float* __restrict__ r1,
              unsigned int* __restrict__ out){
    extern __shared__ float2 sm[];
    float2* plane = sm; float2* scratch = sm + PLANE_F2;
    float2* twt = sm + PLANE_F2 + 64*SW;
    int tid = threadIdx.x, L = tid>>4, v = tid&15;
    int k2 = v>>1, t1 = v&1;
    build_twt(twt, tid, -1.f);
    size_t base = (size_t)blockIdx.x * M2;
    float2 r[8];
    #pragma unroll
    for(int n2=0;n2<8;n2++){
        int zi = v + 16*n2;
        int zs = (zi - 2) & 127;
        float a0 = r0[base + 2*L*128 + zi]     + r1[base + 2*L*128 + zs];
        float a1 = r0[base + (2*L+1)*128 + zi] + r1[base + (2*L+1)*128 + zs];
        r[n2] = make_float2(a0, a1);
    }
    __syncthreads();
    fft128<-1>(r, scratch, L, v, twt);
    #pragma unroll
    for(int j=0;j<8;j++) scratch[L*SW + nidx(k2+8*j+64*t1)] = r[j];
    __syncthreads();
    #pragma unroll
    for(int k=0;k<16;k++){
        int e = tid + k*1024;
        int y = e>>7, z = e&127, p = y>>1;
        float2 H1 = scratch[p*SW + nidx(z)];
        float2 H2 = scratch[p*SW + nidx((128-z)&127)];
        float2 val;
        if ((y&1)==0) val = make_float2(0.5f*(H1.x+H2.x), 0.5f*(H1.y-H2.y));
        else          val = make_float2(0.5f*(H1.y+H2.y), 0.5f*(H2.x-H1.x));
        plane[pidx(e)] = val;
    }
    __syncthreads();
    if (L <= MCUT){
        int zc = nidx(L);
        #pragma unroll
        for(int n2=0;n2<8;n2++) r[n2] = plane[nidx(v+16*n2)*PST + zc];
        fft128<-1>(r, scratch, L, v, twt);
        #pragma unroll
        for(int j=0;j<8;j++) plane[nidx(k2+8*j+64*t1)*PST + zc] = r[j];
    }
    __syncthreads();
    const float s = 1.f/16384.f;
    #pragma unroll
    for(int k=0;k<16;k++){
        int e = tid + k*1024;
        int y = e>>7, z = e&127;
        int mz = (z < 64) ? z : 128 - z;
        if (mz <= MCUT){
            float2 xy;
            if (z <= MCUT) xy = plane[pidx(e)];
            else {
                int y2 = (128-y)&127, z2 = 128-z;
                xy = plane[nidx(y2)*PST + nidx(z2)];
                xy.y = -xy.y;
            }
            out[base+e] = pack_h2(make_float2(xy.x*s, xy.y*s));
        }
    }
}

// Combined inverse -> quad parity grid Q (coalesced uint4 stores).
__global__ void __launch_bounds__(1024, 1)
fft_plane_inv(const unsigned int* __restrict__ inXY,
              const unsigned int* __restrict__ inZ,
              uint4* __restrict__ Q){
    extern __shared__ float2 sm[];
    float2* plane = sm; float2* scratch = sm + PLANE_F2;
    float2* twt = sm + PLANE_F2 + 64*SW;
    int tid = threadIdx.x, L = tid>>4, v = tid&15;
    int k2 = v>>1, t1 = v&1;
    build_twt(twt, tid, 1.f);
    size_t base = (size_t)blockIdx.x * M2;
    float2 r[8];

    // --- Fz plane (Hermitian: rows 0..MCUT computed, 95..127 mirrored) ---
    #pragma unroll
    for(int k=0;k<16;k++){
        int e = tid + k*1024;
        int y = e>>7;
        if (y <= MCUT)      plane[pidx(e)] = unpack_h2(inZ[base+e]);
        else if (y < 95)    plane[pidx(e)] = make_float2(0.f,0.f);
    }
    __syncthreads();
    if (L <= MCUT){
        float2* row = plane + nidx(L)*PST;
        #pragma unroll
        for(int n2=0;n2<8;n2++) r[n2] = row[nidx(v+16*n2)];
        fft128<1>(r, scratch, L, v, twt);
        #pragma unroll
        for(int j=0;j<8;j++) row[nidx(k2+8*j+64*t1)] = r[j];
    }
    __syncthreads();
    #pragma unroll
    for(int k=0;k<16;k++){
        int e = tid + k*1024;
        int y = e>>7;
        if (y >= 95){
            int z = e&127;
            float2 q = plane[nidx(128-y)*PST + nidx(z)];
            plane[pidx(e)] = make_float2(q.x, -q.y);
        }
    }
    __syncthreads();
    {   // packed phase-2: col pair (2L, 2L+1)
        int zc0 = nidx(2*L), zc1 = nidx(2*L+1);
        #pragma unroll
        for(int n2=0;n2<8;n2++){
            int rb = nidx(v+16*n2)*PST;
            float2 A = plane[rb + zc0];
            float2 Bv = plane[rb + zc1];
            r[n2] = make_float2(A.x - Bv.y, A.y + Bv.x);
        }
        fft128<1>(r, scratch, L, v, twt);
        float* pf = (float*)plane;
        #pragma unroll
        for(int j=0;j<8;j++){
            int i = k2+8*j+64*t1;
            int b2 = nidx(i)*PST;
            pf[2*(b2+zc0)] = r[j].x;
            pf[2*(b2+zc1)] = r[j].y;
        }
    }
    __syncthreads();
    float zreg[16];
    #pragma unroll
    for(int k=0;k<16;k++){
        int e = tid + k*1024;
        int y = e>>7, z0 = e&112;
        int my = (y  < 64) ? y  : 128 - y;
        int mzg = (z0 < 64) ? z0 : 113 - z0;
        bool live = (my*my + mzg*mzg <= RR);
        zreg[k] = plane[pidx(e)].x;
        plane[pidx(e)] = live ? unpack_h2(inXY[base+e]) : make_float2(0.f,0.f);
    }
    __syncthreads();
    plane_fft2d_xy(plane, scratch, twt);
    // stage Fz in scratch, pack cells into plane (bits), then quad store
    float* fzs = (float*)scratch;
    #pragma unroll
    for(int k=0;k<16;k++){
        int e = tid + k*1024;
        fzs[e] = zreg[k];
    }
    __syncthreads();
    #pragma unroll
    for(int k=0;k<16;k++){
        int e = tid + k*1024;
        int pi = pidx(e);
        float2 xy = plane[pi];
        uint2 cell = make_uint2(pack_h2(xy), h2u(__floats2half2_rn(fzs[e], 0.f)));
        plane[pi] = *reinterpret_cast<float2*>(&cell);
    }
    __syncthreads();
    int x = blockIdx.x;
    #pragma unroll
    for(int k=0;k<32;k++){
        int oi = tid + k*1024;             // 0..32767
        int ei = oi >> 1, half = oi & 1;
        int variant = ei >> 12, q = ei & 4095;
        int py = variant >> 1, pz = variant & 1;
        int yp = q >> 6, zp = q & 63;
        int y  = (2*yp + py + half) & 127;
        int z0 = 2*zp + pz, z1 = (z0 + 1) & 127;
        int rb = nidx(y)*PST;
        float2 f0 = plane[rb + nidx(z0)];
        float2 f1 = plane[rb + nidx(z1)];
        uint2 c0 = *reinterpret_cast<uint2*>(&f0);
        uint2 c1 = *reinterpret_cast<uint2*>(&f1);
        Q[((size_t)variant*128 + x)*8192 + q*2 + half] =
            make_uint4(c0.x, c0.y, c1.x, c1.y);
    }
}

// ---------------------------------------------------------------------------
__global__ void __launch_bounds__(256)
fft_x_fused(const unsigned int* __restrict__ in,
            unsigned int* __restrict__ outXY,
            unsigned int* __restrict__ outZ){
    __shared__ float2 s[16*SW];
    __shared__ float2 twtF[TWT_F2], twtI[TWT_F2];
    int base = blockIdx.x*16;
    {
        int y  = base >> 7;
        int z0 = base & 127;
        int my = (y  < 64) ? y  : 128 - y;
        int mz = (z0 < 64) ? z0 : 113 - z0;
        if (my*my + mz*mz > RR) return;
    }
    int tid=threadIdx.x, L=tid>>4, v=tid&15;
    build_twt(twtF, tid, -1.f);
    if (tid >= TWT_F2) build_twt(twtI, tid - TWT_F2, 1.f);
    else if (tid < 2*TWT_F2 - 256) build_twt(twtI, tid + (256 - TWT_F2), 1.f);
    float2 r[8];
    #pragma unroll
    for(int k=0;k<8;k++){ int e=tid+k*256; int i=e>>4, l=e&15;
        s[l*SW+nidx(i)] = unpack_h2(in[base + l + i*M2]); }
    __syncthreads();
    #pragma unroll
    for(int n2=0;n2<8;n2++) r[n2] = s[L*SW + nidx(v + 16*n2)];
    fft128<-1>(r, s, L, v, twtF);

    int k2=v>>1, t1=v&1;
    int ylz = base + L;
    int y = ylz>>7, z = ylz&127;
    const float ku = 0.049087385212340526f;
    float ky = (float)((y<64)?y:y-128)*ku;
    float kz = (float)((z<64)?z:z-128)*ku;
    float kyz2 = ky*ky + kz*kz;
    float2 fz[8];
    #pragma unroll
    for(int j=0;j<8;j++){
        int i = k2+8*j+64*t1;
        float kx = (float)((i<64)?i:i-128)*ku;
        float kk = kx*kx + kyz2;
        float coef = 0.f;
        if (kk > 0.f){
            float ikk = 1.f/kk;
            coef = -ikk * __expf(-0.09f*ikk - kk*kk) * (1.f/128.f);
        }
        float pr = r[j].x*coef, pi = r[j].y*coef;
        r[j]  = make_float2(pr*ky + pi*kx, pi*ky - pr*kx);
        fz[j] = make_float2(pi*kz, -pr*kz);
    }

    #pragma unroll
    for(int j=0;j<8;j++){ int i=k2+8*j+64*t1; s[L*SW+nidx(i)] = r[j]; }
    __syncwarp();
    #pragma unroll
    for(int n2=0;n2<8;n2++) r[n2] = s[L*SW + nidx(v + 16*n2)];
    fft128<1>(r, s, L, v, twtI);
    #pragma unroll
    for(int j=0;j<8;j++){ int i=k2+8*j+64*t1; s[L*SW+nidx(i)] = r[j]; }
    __syncthreads();
    #pragma unroll
    for(int k=0;k<8;k++){ int e=tid+k*256; int i=e>>4, l=e&15;
        outXY[base + l + i*M2] = pack_h2(s[l*SW+nidx(i)]); }
    __syncthreads();

    #pragma unroll
    for(int j=0;j<8;j++){ int i=k2+8*j+64*t1; s[L*SW+nidx(i)] = fz[j]; }
    __syncwarp();
    #pragma unroll
    for(int n2=0;n2<8;n2++) r[n2] = s[L*SW + nidx(v + 16*n2)];
    fft128<1>(r, s, L, v, twtI);
    #pragma unroll
    for(int j=0;j<8;j++){ int i=k2+8*j+64*t1; s[L*SW+nidx(i)] = r[j]; }
    __syncthreads();
    #pragma unroll
    for(int k=0;k<8;k++){ int e=tid+k*256; int i=e>>4, l=e&15;
        outZ[base + l + i*M2] = pack_h2(s[l*SW+nidx(i)]); }
}

// ---------------------------------------------------------------------------
// Paint: every particle does exactly 4 aligned float4 REDs.
__global__ void paint_kernel(const float* __restrict__ pos,
                             float* __restrict__ R0, float* __restrict__ R1,
                             int N){
    int n = blockIdx.x*256 + threadIdx.x;
    if (n >= N) return;
    float px = pos[3*n+0], py = pos[3*n+1], pz = pos[3*n+2];
    float f0x = floorf(px), f0y = floorf(py), f0z = floorf(pz);
    int ix = ((int)f0x)&127, iy = ((int)f0y)&127, iz = ((int)f0z)&127;
    float dx = px-f0x, dy = py-f0y, dz = pz-f0z;
    float wx[2]={1.f-dx,dx}, wy[2]={1.f-dy,dy};
    float wz0 = 1.f-dz, wz1 = dz;
    int xi[2]={ix,(ix+1)&127}, yi[2]={iy,(iy+1)&127};
    int lanez = iz & 3;
    float* Gd;
    int zb;
    float v0=0.f, v1=0.f, v2=0.f, v3=0.f;
    if (lanez == 0){ Gd = R0; zb = iz & ~3;       v0=wz0; v1=wz1; }
    else if (lanez == 1){ Gd = R0; zb = iz & ~3;  v1=wz0; v2=wz1; }
    else if (lanez == 2){ Gd = R0; zb = iz & ~3;  v2=wz0; v3=wz1; }
    else { Gd = R1; zb = (iz-2) & ~3;             v1=wz0; v2=wz1; }
#pragma unroll
    for(int a=0;a<2;a++)
#pragma unroll
    for(int b=0;b<2;b++){
        float wab = wx[a]*wy[b];
        atomicAdd((float4*)(Gd + xi[a]*M2 + yi[b]*MESHN + zb),
                  make_float4(wab*v0, wab*v1, wab*v2, wab*v3));
    }
}

__global__ void copy_pos_kernel(const float4* __restrict__ pos4,
                                float4* __restrict__ out4, int n4){
    int i = blockIdx.x*256 + threadIdx.x;
    if (i < n4) out4[i] = pos4[i];
}

// Gather from quad grid: 4 aligned 16B loads per particle (2 sectors).
__global__ void gather_kernel(const float* __restrict__ pos,
                              const float* __restrict__ vel,
                              const float* __restrict__ drift,
                              const uint4* __restrict__ Q,
                              float* __restrict__ out, int N){
    int n = blockIdx.x*256 + threadIdx.x;
    if (n >= N) return;
    float px = pos[3*n+0], py = pos[3*n+1], pz = pos[3*n+2];
    float f0x = floorf(px), f0y = floorf(py), f0z = floorf(pz);
    int ix = ((int)f0x)&127, iy = ((int)f0y)&127, iz = ((int)f0z)&127;
    float dx = px-f0x, dy = py-f0y, dz = pz-f0z;
    float wx[2]={1.f-dx,dx};
    float wy0 = 1.f-dy, wy1 = dy;
    float wz0 = 1.f-dz, wz1 = dz;
    int xi[2]={ix,(ix+1)&127};
    int variant = (iy&1)*2 + (iz&1);
    int yp = iy>>1, zp = iz>>1;
    float fx=0.f, fy=0.f, fzv=0.f;
#pragma unroll
    for(int a=0;a<2;a++){
        size_t bi = ((size_t)variant*128 + xi[a])*8192 + (size_t)(yp*64 + zp)*2;
        uint4 u0 = Q[bi];
        uint4 u1 = Q[bi+1];
        float w = wx[a];
        float w00 = w*wy0*wz0, w01 = w*wy0*wz1;
        float w10 = w*wy1*wz0, w11 = w*wy1*wz1;
        float2 a00 = unpack_h2(u0.x); float z00 = __low2float(u2h(u0.y));
        float2 a01 = unpack_h2(u0.z); float z01 = __low2float(u2h(u0.w));
        float2 a10 = unpack_h2(u1.x); float z10 = __low2float(u2h(u1.y));
        float2 a11 = unpack_h2(u1.z); float z11 = __low2float(u2h(u1.w));
        fx  += w00*a00.x + w01*a01.x + w10*a10.x + w11*a11.x;
        fy  += w00*a00.y + w01*a01.y + w10*a10.y + w11*a11.y;
        fzv += w00*z00  + w01*z01  + w10*z10  + w11*z11;
    }
    float sc = 0.2f / drift[0];
    float* ov = out + (size_t)3*N;
    ov[3*n+0]=vel[3*n+0]+fx*sc;
    ov[3*n+1]=vel[3*n+1]+fy*sc;
    ov[3*n+2]=vel[3*n+2]+fzv*sc;
}

// ---------------------------------------------------------------------------
extern "C" void kernel_launch(void* const* d_in, const int* in_sizes, int n_in,
                              void* d_out, int out_size){
    const float* pos   = (const float*)d_in[0];
    const float* vel   = (const float*)d_in[1];
    const float* drift = (const float*)d_in[2];
    float* out = (float*)d_out;
    int N = in_sizes[0] / 3;

    void *pR0,*pR1,*pA,*pB,*pC,*pQ;
    cudaGetSymbolAddress(&pR0, g_real);
    cudaGetSymbolAddress(&pR1, g_realB);
    cudaGetSymbolAddress(&pA, g_A);
    cudaGetSymbolAddress(&pB, g_B);
    cudaGetSymbolAddress(&pC, g_C);
    cudaGetSymbolAddress(&pQ, g_Q);
    float* R0 = (float*)pR0;
    float* R1 = (float*)pR1;
    unsigned int* A = (unsigned int*)pA;
    unsigned int* B = (unsigned int*)pB;
    unsigned int* C = (unsigned int*)pC;
    uint4* Q = (uint4*)pQ;

    cudaFuncSetAttribute(fft_plane_fwd, cudaFuncAttributeMaxDynamicSharedMemorySize, SMEM_PLANE);
    cudaFuncSetAttribute(fft_plane_inv, cudaFuncAttributeMaxDynamicSharedMemorySize, SMEM_PLANE);

    cudaStream_t s1;
    cudaEvent_t ev0, ev1, evM;
    cudaStreamCreateWithFlags(&s1, cudaStreamNonBlocking);
    cudaEventCreateWithFlags(&ev0, cudaEventDisableTiming);
    cudaEventCreateWithFlags(&ev1, cudaEventDisableTiming);
    cudaEventCreateWithFlags(&evM, cudaEventDisableTiming);

    // Side stream: memset R1 (overlaps memset R0) then pos passthrough.
    cudaEventRecord(ev0, 0);
    cudaStreamWaitEvent(s1, ev0, 0);
    cudaMemsetAsync(R1, 0, (size_t)M3*sizeof(float), s1);
    cudaEventRecord(evM, s1);
    int n4 = (3*N)/4;
    copy_pos_kernel<<<(n4+255)/256, 256, 0, s1>>>((const float4*)pos, (float4*)out, n4);
    cudaEventRecord(ev1, s1);

    // Main stream
    cudaMemsetAsync(R0, 0, (size_t)M3*sizeof(float), 0);
    cudaStreamWaitEvent(0, evM, 0);
    paint_kernel<<<(N+255)/256, 256>>>(pos, R0, R1, N);

    fft_plane_fwd<<<128, 1024, SMEM_PLANE>>>(R0, R1, B);
    fft_x_fused<<<1024, 256>>>(B, A, C);
    fft_plane_inv<<<128, 1024, SMEM_PLANE>>>(A, C, Q);

    cudaStreamWaitEvent(0, ev1, 0);
    gather_kernel<<<(N+255)/256, 256>>>(pos, vel, drift, Q, out, N);
}